// round 14
// baseline (speedup 1.0000x reference)
#include <cuda_runtime.h>

// Resample2d (FlowNet2 bilinear warp), fixed shape B=4, C=64, H=384, W=512.
//
// R13: R1's proven-optimal per-tile geometry (1 px/thread, warps = 32
// consecutive x, 4 scalar tap gathers reused over 64 channels — the measured
// L1-wavefront floor), made PERSISTENT: exactly one wave of 1184 blocks
// (148 SM x 8), each grid-striding over pixel tiles. Removes the 2.6-wave
// launch structure (2 wave transitions + 0.6-wave ragged tail + cross-CTA
// L1tex-queue spread at wave boundaries) that left ~17% of the L1 pipe idle.

static constexpr int B = 4;
static constexpr int C = 64;
static constexpr int H = 384;
static constexpr int W = 512;
static constexpr int HW = H * W;
static constexpr int NPIX = B * H * W;           // 786432
static constexpr int NTILES = NPIX / 256;        // 3072 tiles of 256 px
static constexpr int NBLOCKS = 148 * 8;          // one full wave

__global__ __launch_bounds__(256) void resample2d_kernel(
    const float* __restrict__ in1,
    const float* __restrict__ flow,
    float* __restrict__ out)
{
    for (int tile = blockIdx.x; tile < NTILES; tile += NBLOCKS) {
        int idx = tile * 256 + threadIdx.x;

        int x = idx & (W - 1);          // W = 512 = 2^9
        int t = idx >> 9;               // b*H + y
        int y = t % H;
        int b = t / H;

        int pix = y * W + x;
        const float* fptr = flow + (size_t)b * 2 * HW;
        float dx = fptr[pix];
        float dy = fptr[HW + pix];

        float xf = (float)x + dx;
        float yf = (float)y + dy;
        float x0f = floorf(xf);
        float y0f = floorf(yf);
        float a  = xf - x0f;            // frac x
        float bw = yf - y0f;            // frac y

        int x0i = (int)x0f;
        int y0i = (int)y0f;
        int x0 = min(max(x0i,     0), W - 1);
        int x1 = min(max(x0i + 1, 0), W - 1);
        int y0 = min(max(y0i,     0), H - 1);
        int y1 = min(max(y0i + 1, 0), H - 1);

        float w00 = (1.0f - a) * (1.0f - bw);
        float w10 = a * (1.0f - bw);
        float w01 = (1.0f - a) * bw;
        float w11 = a * bw;

        int i00 = y0 * W + x0;
        int i10 = y0 * W + x1;
        int i01 = y1 * W + x0;
        int i11 = y1 * W + x1;

        const float* p = in1 + (size_t)b * C * HW;
        float*       o = out + (size_t)b * C * HW + pix;

        #pragma unroll 4
        for (int c = 0; c < C; ++c) {
            size_t off = (size_t)c * HW;
            float v00 = __ldg(p + off + i00);
            float v10 = __ldg(p + off + i10);
            float v01 = __ldg(p + off + i01);
            float v11 = __ldg(p + off + i11);
            o[off] = w00 * v00 + w10 * v10 + w01 * v01 + w11 * v11;
        }
    }
}

extern "C" void kernel_launch(void* const* d_in, const int* in_sizes, int n_in,
                              void* d_out, int out_size)
{
    const float* in1  = (const float*)d_in[0];
    const float* flow = (const float*)d_in[1];
    float*       out  = (float*)d_out;

    resample2d_kernel<<<NBLOCKS, 256>>>(in1, flow, out);
}

// round 15
// speedup vs baseline: 1.1072x; 1.1072x over previous
#include <cuda_runtime.h>

// Resample2d (FlowNet2 bilinear warp), fixed shape B=4, C=64, H=384, W=512.
//
// R14: R1's proven per-warp gather geometry (warp = 32 consecutive x on one
// row, 4 scalar tap gathers reused over 64 channels — the measured L1
// wavefront floor) with a 32x8 2D block tile instead of 256x1:
// the 8 warps' tap rows overlap (y-1..y+9), cutting the block's L2/DRAM
// gather footprint ~2.5x per channel. L1 wavefronts are unchanged by
// construction; the win target is higher L1 issue density via lower miss
// latency.

static constexpr int B = 4;
static constexpr int C = 64;
static constexpr int H = 384;
static constexpr int W = 512;
static constexpr int HW = H * W;

__global__ __launch_bounds__(256) void resample2d_kernel(
    const float* __restrict__ in1,
    const float* __restrict__ flow,
    float* __restrict__ out)
{
    int x = blockIdx.x * 32 + (threadIdx.x & 31);
    int y = blockIdx.y * 8 + (threadIdx.x >> 5);
    int b = blockIdx.z;

    int pix = y * W + x;
    const float* fptr = flow + (size_t)b * 2 * HW;
    float dx = fptr[pix];
    float dy = fptr[HW + pix];

    float xf = (float)x + dx;
    float yf = (float)y + dy;
    float x0f = floorf(xf);
    float y0f = floorf(yf);
    float a  = xf - x0f;            // frac x
    float bw = yf - y0f;            // frac y

    int x0i = (int)x0f;
    int y0i = (int)y0f;
    int x0 = min(max(x0i,     0), W - 1);
    int x1 = min(max(x0i + 1, 0), W - 1);
    int y0 = min(max(y0i,     0), H - 1);
    int y1 = min(max(y0i + 1, 0), H - 1);

    float w00 = (1.0f - a) * (1.0f - bw);
    float w10 = a * (1.0f - bw);
    float w01 = (1.0f - a) * bw;
    float w11 = a * bw;

    int i00 = y0 * W + x0;
    int i10 = y0 * W + x1;
    int i01 = y1 * W + x0;
    int i11 = y1 * W + x1;

    const float* p = in1 + (size_t)b * C * HW;
    float*       o = out + (size_t)b * C * HW + pix;

    #pragma unroll 4
    for (int c = 0; c < C; ++c) {
        size_t off = (size_t)c * HW;
        float v00 = __ldg(p + off + i00);
        float v10 = __ldg(p + off + i10);
        float v01 = __ldg(p + off + i01);
        float v11 = __ldg(p + off + i11);
        o[off] = w00 * v00 + w10 * v10 + w01 * v01 + w11 * v11;
    }
}

extern "C" void kernel_launch(void* const* d_in, const int* in_sizes, int n_in,
                              void* d_out, int out_size)
{
    const float* in1  = (const float*)d_in[0];
    const float* flow = (const float*)d_in[1];
    float*       out  = (float*)d_out;

    dim3 grid(W / 32, H / 8, B);    // 16 x 48 x 4 = 3072 blocks
    resample2d_kernel<<<grid, 256>>>(in1, flow, out);
}